// round 1
// baseline (speedup 1.0000x reference)
#include <cuda_runtime.h>
#include <math.h>

#define B_ 1024
#define N_ 50000
#define D_ 256
#define NV4 (N_ / 4)   // 12500 float4 per row

// Cross-block accumulators (double for deterministic-enough precision).
// 0: sum_b (d0 - lse0*sx)  [recon/merged]
// 1: sum_b (d1 - lse1*sx)  [text]
// 2: sum_b (d2 - lse2*sx)  [rec]
// 3: sum (1 + lv - mu^2 - e^lv)
// 4: sum (-0.5*plv - 0.5*(z-pmu)^2 e^{-plv} + 0.5 z^2)
// 5: sum ((mu-pmu)^2 + e^lv + e^plv - 2 sqrt(e^lv e^plv))
__device__ double g_acc[8];

__global__ void zero_acc_kernel() {
    if (threadIdx.x < 8) g_acc[threadIdx.x] = 0.0;
}

// One block per batch row. Single pass over all three logits matrices + x.
__global__ __launch_bounds__(1024, 1)
void bce_rows_kernel(const float4* __restrict__ recon,
                     const float4* __restrict__ xmat,
                     const float4* __restrict__ text,
                     const float4* __restrict__ rec)
{
    const int b = blockIdx.x;
    const size_t base = (size_t)b * NV4;
    const float4* __restrict__ R = recon + base;
    const float4* __restrict__ X = xmat + base;
    const float4* __restrict__ T = text + base;
    const float4* __restrict__ C = rec + base;

    float se0 = 0.f, se1 = 0.f, se2 = 0.f;
    float d0 = 0.f, d1 = 0.f, d2 = 0.f;
    float sx = 0.f;

    for (int i = threadIdx.x; i < NV4; i += blockDim.x) {
        float4 r = R[i];
        float4 x = X[i];
        float4 t = T[i];
        float4 c = C[i];

        se0 += __expf(r.x) + __expf(r.y) + __expf(r.z) + __expf(r.w);
        se1 += __expf(t.x) + __expf(t.y) + __expf(t.z) + __expf(t.w);
        se2 += __expf(c.x) + __expf(c.y) + __expf(c.z) + __expf(c.w);

        d0 += r.x * x.x + r.y * x.y + r.z * x.z + r.w * x.w;
        d1 += t.x * x.x + t.y * x.y + t.z * x.z + t.w * x.w;
        d2 += c.x * x.x + c.y * x.y + c.z * x.z + c.w * x.w;

        sx += x.x + x.y + x.z + x.w;
    }

    // Block reduction of 7 scalars: warp shuffle, then warp-0 across 32 warps.
    __shared__ float sh[7][32];
    float vals[7] = {se0, se1, se2, d0, d1, d2, sx};
    const int lane = threadIdx.x & 31;
    const int w = threadIdx.x >> 5;

    #pragma unroll
    for (int j = 0; j < 7; j++) {
        float v = vals[j];
        #pragma unroll
        for (int o = 16; o > 0; o >>= 1) v += __shfl_down_sync(0xffffffffu, v, o);
        if (lane == 0) sh[j][w] = v;
    }
    __syncthreads();

    if (w == 0) {
        #pragma unroll
        for (int j = 0; j < 7; j++) {
            float v = sh[j][lane];
            #pragma unroll
            for (int o = 16; o > 0; o >>= 1) v += __shfl_down_sync(0xffffffffu, v, o);
            vals[j] = v;
        }
        if (lane == 0) {
            // logsumexp without max-subtraction: safe for |logit| < ~80.
            double lse0 = log((double)vals[0]);
            double lse1 = log((double)vals[1]);
            double lse2 = log((double)vals[2]);
            double sxd = (double)vals[6];
            atomicAdd(&g_acc[0], (double)vals[3] - lse0 * sxd);
            atomicAdd(&g_acc[1], (double)vals[4] - lse1 * sxd);
            atomicAdd(&g_acc[2], (double)vals[5] - lse2 * sxd);
        }
    }
}

// Flat elementwise sums over [B, D] for KLD1 / KLD2 / Wasserstein.
__global__ __launch_bounds__(256)
void dterms_kernel(const float* __restrict__ z,
                   const float* __restrict__ mu,
                   const float* __restrict__ lv,
                   const float* __restrict__ pmu,
                   const float* __restrict__ plv)
{
    const int n = B_ * D_;
    float k1 = 0.f, k2 = 0.f, wv = 0.f;
    for (int i = blockIdx.x * blockDim.x + threadIdx.x; i < n;
         i += gridDim.x * blockDim.x) {
        float m  = mu[i];
        float l  = lv[i];
        float pm = pmu[i];
        float pl = plv[i];
        float zz = z[i];

        float el  = __expf(l);
        float epl = __expf(pl);

        k1 += 1.f + l - m * m - el;

        float dz = zz - pm;
        k2 += -0.5f * pl - 0.5f * dz * dz * __expf(-pl) + 0.5f * zz * zz;

        float dm = m - pm;
        wv += dm * dm + el + epl - 2.f * sqrtf(el * epl);
    }

    __shared__ float sh[3][8];
    float vals[3] = {k1, k2, wv};
    const int lane = threadIdx.x & 31;
    const int w = threadIdx.x >> 5;
    #pragma unroll
    for (int j = 0; j < 3; j++) {
        float v = vals[j];
        #pragma unroll
        for (int o = 16; o > 0; o >>= 1) v += __shfl_down_sync(0xffffffffu, v, o);
        if (lane == 0) sh[j][w] = v;
    }
    __syncthreads();
    if (w == 0 && lane == 0) {
        #pragma unroll
        for (int j = 0; j < 3; j++) {
            float v = 0.f;
            #pragma unroll
            for (int q = 0; q < 8; q++) v += sh[j][q];
            atomicAdd(&g_acc[3 + j], (double)v);
        }
    }
}

__global__ void finalize_kernel(float* __restrict__ out) {
    const double invBN = 1.0 / ((double)B_ * (double)N_);
    const double invBD = 1.0 / ((double)B_ * (double)D_);

    double bce_merged = -g_acc[0] * invBN;
    double bce_text   = -g_acc[1] * invBN;
    double bce_rec    = -g_acc[2] * invBN;
    double BCE = (bce_merged + bce_text + bce_rec) / 3.0;

    double KLD1 = -0.5 * g_acc[3] * invBD;
    double KLD2 = g_acc[4] * invBD;          // ANNEAL = 1
    double wass = g_acc[5] / (double)B_;

    double l = BCE + 0.5 * (KLD1 + KLD2) + 1.0 * wass;  // ANNEAL/2, EPSILON=1

    out[0] = (float)l;
    out[1] = (float)BCE;
    out[2] = (float)wass;
    out[3] = (float)bce_rec;
    out[4] = (float)bce_text;
    out[5] = (float)bce_merged;
}

extern "C" void kernel_launch(void* const* d_in, const int* in_sizes, int n_in,
                              void* d_out, int out_size) {
    const float* recon = (const float*)d_in[0];
    const float* x     = (const float*)d_in[1];
    const float* z     = (const float*)d_in[2];
    const float* mu    = (const float*)d_in[3];
    const float* lv    = (const float*)d_in[4];
    const float* text  = (const float*)d_in[5];
    const float* rec   = (const float*)d_in[6];
    const float* pmu   = (const float*)d_in[7];
    const float* plv   = (const float*)d_in[8];
    // d_in[9] = train_items, unused by the loss

    zero_acc_kernel<<<1, 32>>>();
    bce_rows_kernel<<<B_, 1024>>>((const float4*)recon, (const float4*)x,
                                  (const float4*)text, (const float4*)rec);
    dterms_kernel<<<208, 256>>>(z, mu, lv, pmu, plv);
    finalize_kernel<<<1, 1>>>((float*)d_out);
}

// round 2
// speedup vs baseline: 1.0240x; 1.0240x over previous
#include <cuda_runtime.h>
#include <math.h>

#define B_ 1024
#define N_ 50000
#define D_ 256
#define NV4 (N_ / 4)      // 12500 float4 per row
#define TPB 1024
#define PAIRS 6           // 6 * 2048 = 12288; remainder 212 handled separately

// Cross-block accumulators (doubles).
// 0..2: sum_b (dot - lse*sx) for merged/text/rec
// 3: sum(1 + lv - mu^2 - e^lv)
// 4: sum(-0.5*plv - 0.5*(z-pmu)^2 e^{-plv} + 0.5 z^2)
// 5: sum((mu-pmu)^2 + e^lv + e^plv - 2 sqrt(e^lv e^plv))
__device__ double g_acc[6];
__device__ unsigned int g_cnt;

__device__ __forceinline__ float sum_exp4(float4 v) {
    return __expf(v.x) + __expf(v.y) + __expf(v.z) + __expf(v.w);
}
__device__ __forceinline__ float dot4(float4 a, float4 b) {
    return a.x * b.x + a.y * b.y + a.z * b.z + a.w * b.w;
}

__global__ __launch_bounds__(TPB, 1)
void recvae_fused_kernel(const float4* __restrict__ recon,
                         const float4* __restrict__ xmat,
                         const float4* __restrict__ text,
                         const float4* __restrict__ rec,
                         const float*  __restrict__ z,
                         const float*  __restrict__ mu,
                         const float*  __restrict__ lv,
                         const float*  __restrict__ pmu,
                         const float*  __restrict__ plv,
                         float* __restrict__ out)
{
    const int b   = blockIdx.x;
    const int tid = threadIdx.x;
    const size_t base = (size_t)b * NV4;
    const float4* __restrict__ R = recon + base;
    const float4* __restrict__ X = xmat  + base;
    const float4* __restrict__ T = text  + base;
    const float4* __restrict__ C = rec   + base;

    float se0 = 0.f, se1 = 0.f, se2 = 0.f;
    float d0 = 0.f, d1 = 0.f, d2 = 0.f;
    float sx = 0.f;

    // Main pass: unroll x2, all 8 loads issued before compute (MLP ~8/thread).
    int i = tid;
    #pragma unroll 1
    for (int p = 0; p < PAIRS; p++, i += 2 * TPB) {
        float4 r0 = R[i];
        float4 x0 = X[i];
        float4 t0 = T[i];
        float4 c0 = C[i];
        float4 r1 = R[i + TPB];
        float4 x1 = X[i + TPB];
        float4 t1 = T[i + TPB];
        float4 c1 = C[i + TPB];

        se0 += sum_exp4(r0) + sum_exp4(r1);
        se1 += sum_exp4(t0) + sum_exp4(t1);
        se2 += sum_exp4(c0) + sum_exp4(c1);
        d0  += dot4(r0, x0) + dot4(r1, x1);
        d1  += dot4(t0, x0) + dot4(t1, x1);
        d2  += dot4(c0, x0) + dot4(c1, x1);
        sx  += x0.x + x0.y + x0.z + x0.w + x1.x + x1.y + x1.z + x1.w;
    }
    // remainder: i = tid + 12288; active for tid < 212
    if (i < NV4) {
        float4 r0 = R[i];
        float4 x0 = X[i];
        float4 t0 = T[i];
        float4 c0 = C[i];
        se0 += sum_exp4(r0);
        se1 += sum_exp4(t0);
        se2 += sum_exp4(c0);
        d0  += dot4(r0, x0);
        d1  += dot4(t0, x0);
        d2  += dot4(c0, x0);
        sx  += x0.x + x0.y + x0.z + x0.w;
    }

    // Fused [B,D] terms: block b covers flat chunk [b*256, b*256+256).
    float k1 = 0.f, k2 = 0.f, wv = 0.f;
    if (tid < D_) {
        const int idx = b * D_ + tid;
        float m  = mu[idx];
        float l  = lv[idx];
        float pm = pmu[idx];
        float pl = plv[idx];
        float zz = z[idx];

        float el  = __expf(l);
        float epl = __expf(pl);

        k1 = 1.f + l - m * m - el;

        float dz = zz - pm;
        k2 = -0.5f * pl - 0.5f * dz * dz * __expf(-pl) + 0.5f * zz * zz;

        float dm = m - pm;
        wv = dm * dm + el + epl - 2.f * sqrtf(el * epl);
    }

    // Block reduction of 10 scalars.
    __shared__ float sh[10][32];
    float vals[10] = {se0, se1, se2, d0, d1, d2, sx, k1, k2, wv};
    const int lane = tid & 31;
    const int w    = tid >> 5;

    #pragma unroll
    for (int j = 0; j < 10; j++) {
        float v = vals[j];
        #pragma unroll
        for (int o = 16; o > 0; o >>= 1) v += __shfl_down_sync(0xffffffffu, v, o);
        if (lane == 0) sh[j][w] = v;
    }
    __syncthreads();

    if (w == 0) {
        #pragma unroll
        for (int j = 0; j < 10; j++) {
            float v = sh[j][lane];
            #pragma unroll
            for (int o = 16; o > 0; o >>= 1) v += __shfl_down_sync(0xffffffffu, v, o);
            vals[j] = v;
        }
        if (lane == 0) {
            // per-row:  dot - log(sumexp) * sum(x)   (logits ~N(0,1): no max-sub needed)
            double lse0 = log((double)vals[0]);
            double lse1 = log((double)vals[1]);
            double lse2 = log((double)vals[2]);
            double sxd  = (double)vals[6];
            atomicAdd(&g_acc[0], (double)vals[3] - lse0 * sxd);
            atomicAdd(&g_acc[1], (double)vals[4] - lse1 * sxd);
            atomicAdd(&g_acc[2], (double)vals[5] - lse2 * sxd);
            atomicAdd(&g_acc[3], (double)vals[7]);
            atomicAdd(&g_acc[4], (double)vals[8]);
            atomicAdd(&g_acc[5], (double)vals[9]);

            __threadfence();
            unsigned done = atomicAdd(&g_cnt, 1u);
            if (done == gridDim.x - 1) {
                // last block: finalize + reset accumulators for next replay
                double a[6];
                #pragma unroll
                for (int j = 0; j < 6; j++) a[j] = atomicAdd(&g_acc[j], 0.0);

                const double invBN = 1.0 / ((double)B_ * (double)N_);
                const double invBD = 1.0 / ((double)B_ * (double)D_);

                double bce_merged = -a[0] * invBN;
                double bce_text   = -a[1] * invBN;
                double bce_rec    = -a[2] * invBN;
                double BCE = (bce_merged + bce_text + bce_rec) / 3.0;

                double KLD1 = -0.5 * a[3] * invBD;
                double KLD2 = a[4] * invBD;           // ANNEAL = 1
                double wass = a[5] / (double)B_;

                double lval = BCE + 0.5 * (KLD1 + KLD2) + wass;  // ANNEAL/2, EPSILON=1

                out[0] = (float)lval;
                out[1] = (float)BCE;
                out[2] = (float)wass;
                out[3] = (float)bce_rec;
                out[4] = (float)bce_text;
                out[5] = (float)bce_merged;

                #pragma unroll
                for (int j = 0; j < 6; j++) g_acc[j] = 0.0;
                g_cnt = 0u;
            }
        }
    }
}

extern "C" void kernel_launch(void* const* d_in, const int* in_sizes, int n_in,
                              void* d_out, int out_size) {
    const float* recon = (const float*)d_in[0];
    const float* x     = (const float*)d_in[1];
    const float* z     = (const float*)d_in[2];
    const float* mu    = (const float*)d_in[3];
    const float* lv    = (const float*)d_in[4];
    const float* text  = (const float*)d_in[5];
    const float* rec   = (const float*)d_in[6];
    const float* pmu   = (const float*)d_in[7];
    const float* plv   = (const float*)d_in[8];
    // d_in[9] = train_items, unused by the loss

    recvae_fused_kernel<<<B_, TPB>>>((const float4*)recon, (const float4*)x,
                                     (const float4*)text, (const float4*)rec,
                                     z, mu, lv, pmu, plv, (float*)d_out);
}

// round 3
// speedup vs baseline: 1.1633x; 1.1360x over previous
#include <cuda_runtime.h>
#include <math.h>

#define B_ 1024
#define N_ 50000
#define D_ 256
#define NV4 (N_ / 4)        // 12500 float4 per row
#define WPR 25              // warps per row: 24 full segs of 512 + 1 seg of 212
#define SEG 512             // float4 per full warp segment
#define P1_TPB 256
#define P1_GRID (B_ * WPR / 8)   // 3200 blocks

// Per-row partials: 0..2 sumexp(merged,text,rec), 3..5 dot, 6 sum(x)
__device__ double g_row[B_][7];
// Global scalars: 0..2 BCE sums, 3 KLD1 sum, 4 KLD2 sum, 5 wasserstein sum
__device__ double g_acc[6];
__device__ unsigned int g_cnt;

__device__ __forceinline__ float sum_exp4(float4 v) {
    return __expf(v.x) + __expf(v.y) + __expf(v.z) + __expf(v.w);
}
__device__ __forceinline__ float dot4(float4 a, float4 b) {
    return a.x * b.x + a.y * b.y + a.z * b.z + a.w * b.w;
}

// Pass 1: warp-centric, barrier-free streaming reduce over the 3 logits + x.
__global__ __launch_bounds__(P1_TPB, 4)
void pass1_kernel(const float4* __restrict__ recon,
                  const float4* __restrict__ xmat,
                  const float4* __restrict__ text,
                  const float4* __restrict__ rec)
{
    const int lane = threadIdx.x & 31;
    const int gw   = (blockIdx.x * P1_TPB + threadIdx.x) >> 5;  // global warp id
    const int row  = gw / WPR;
    const int seg  = gw - row * WPR;

    const size_t base = (size_t)row * NV4;
    const float4* __restrict__ R = recon + base;
    const float4* __restrict__ X = xmat  + base;
    const float4* __restrict__ T = text  + base;
    const float4* __restrict__ C = rec   + base;

    float se0 = 0.f, se1 = 0.f, se2 = 0.f;
    float d0 = 0.f, d1 = 0.f, d2 = 0.f;
    float sx = 0.f;

    if (seg < 24) {
        // full 512-float4 segment: 8 unrolled pairs, 8 LDG.128 in flight
        int i = seg * SEG + lane;
        #pragma unroll 1
        for (int p = 0; p < 8; p++, i += 64) {
            float4 r0 = __ldcs(&R[i]);
            float4 x0 = __ldcs(&X[i]);
            float4 t0 = __ldcs(&T[i]);
            float4 c0 = __ldcs(&C[i]);
            float4 r1 = __ldcs(&R[i + 32]);
            float4 x1 = __ldcs(&X[i + 32]);
            float4 t1 = __ldcs(&T[i + 32]);
            float4 c1 = __ldcs(&C[i + 32]);

            se0 += sum_exp4(r0) + sum_exp4(r1);
            se1 += sum_exp4(t0) + sum_exp4(t1);
            se2 += sum_exp4(c0) + sum_exp4(c1);
            d0  += dot4(r0, x0) + dot4(r1, x1);
            d1  += dot4(t0, x0) + dot4(t1, x1);
            d2  += dot4(c0, x0) + dot4(c1, x1);
            sx  += x0.x + x0.y + x0.z + x0.w + x1.x + x1.y + x1.z + x1.w;
        }
    } else {
        // tail segment: columns [12288, 12500) = 212 float4
        for (int i = 24 * SEG + lane; i < NV4; i += 32) {
            float4 r0 = __ldcs(&R[i]);
            float4 x0 = __ldcs(&X[i]);
            float4 t0 = __ldcs(&T[i]);
            float4 c0 = __ldcs(&C[i]);
            se0 += sum_exp4(r0);
            se1 += sum_exp4(t0);
            se2 += sum_exp4(c0);
            d0  += dot4(r0, x0);
            d1  += dot4(t0, x0);
            d2  += dot4(c0, x0);
            sx  += x0.x + x0.y + x0.z + x0.w;
        }
    }

    // Warp reduce 7 scalars, one double atomicAdd each per warp.
    float vals[7] = {se0, se1, se2, d0, d1, d2, sx};
    #pragma unroll
    for (int j = 0; j < 7; j++) {
        float v = vals[j];
        #pragma unroll
        for (int o = 16; o > 0; o >>= 1) v += __shfl_down_sync(0xffffffffu, v, o);
        vals[j] = v;
    }
    if (lane == 0) {
        #pragma unroll
        for (int j = 0; j < 7; j++) atomicAdd(&g_row[row][j], (double)vals[j]);
    }
}

// Pass 2: per-row finalize of BCE terms + [B,D] elementwise terms + global finalize.
__global__ __launch_bounds__(256)
void pass2_kernel(const float* __restrict__ z,
                  const float* __restrict__ mu,
                  const float* __restrict__ lv,
                  const float* __restrict__ pmu,
                  const float* __restrict__ plv,
                  float* __restrict__ out)
{
    const int b   = blockIdx.x;      // 1024
    const int t   = threadIdx.x;     // 256 == D_
    const int idx = b * D_ + t;

    float m  = mu[idx];
    float l  = lv[idx];
    float pm = pmu[idx];
    float pl = plv[idx];
    float zz = z[idx];

    float el  = __expf(l);
    float epl = __expf(pl);

    float k1 = 1.f + l - m * m - el;
    float dz = zz - pm;
    float k2 = -0.5f * pl - 0.5f * dz * dz * __expf(-pl) + 0.5f * zz * zz;
    float dm = m - pm;
    float wv = dm * dm + el + epl - 2.f * sqrtf(el * epl);

    __shared__ float sh[3][8];
    float vals[3] = {k1, k2, wv};
    const int lane = t & 31;
    const int w    = t >> 5;
    #pragma unroll
    for (int j = 0; j < 3; j++) {
        float v = vals[j];
        #pragma unroll
        for (int o = 16; o > 0; o >>= 1) v += __shfl_down_sync(0xffffffffu, v, o);
        if (lane == 0) sh[j][w] = v;
    }
    __syncthreads();

    if (t == 0) {
        float s0 = 0.f, s1 = 0.f, s2 = 0.f;
        #pragma unroll
        for (int q = 0; q < 8; q++) { s0 += sh[0][q]; s1 += sh[1][q]; s2 += sh[2][q]; }

        double se0 = g_row[b][0], se1 = g_row[b][1], se2 = g_row[b][2];
        double dd0 = g_row[b][3], dd1 = g_row[b][4], dd2 = g_row[b][5];
        double sxd = g_row[b][6];

        atomicAdd(&g_acc[0], dd0 - log(se0) * sxd);
        atomicAdd(&g_acc[1], dd1 - log(se1) * sxd);
        atomicAdd(&g_acc[2], dd2 - log(se2) * sxd);
        atomicAdd(&g_acc[3], (double)s0);
        atomicAdd(&g_acc[4], (double)s1);
        atomicAdd(&g_acc[5], (double)s2);

        // reset this row's partials for the next graph replay
        #pragma unroll
        for (int j = 0; j < 7; j++) g_row[b][j] = 0.0;

        __threadfence();
        unsigned done = atomicAdd(&g_cnt, 1u);
        if (done == gridDim.x - 1) {
            double a[6];
            #pragma unroll
            for (int j = 0; j < 6; j++) a[j] = atomicAdd(&g_acc[j], 0.0);

            const double invBN = 1.0 / ((double)B_ * (double)N_);
            const double invBD = 1.0 / ((double)B_ * (double)D_);

            double bce_merged = -a[0] * invBN;
            double bce_text   = -a[1] * invBN;
            double bce_rec    = -a[2] * invBN;
            double BCE = (bce_merged + bce_text + bce_rec) / 3.0;

            double KLD1 = -0.5 * a[3] * invBD;
            double KLD2 = a[4] * invBD;            // ANNEAL = 1
            double wass = a[5] / (double)B_;

            double lval = BCE + 0.5 * (KLD1 + KLD2) + wass;  // ANNEAL/2, EPSILON=1

            out[0] = (float)lval;
            out[1] = (float)BCE;
            out[2] = (float)wass;
            out[3] = (float)bce_rec;
            out[4] = (float)bce_text;
            out[5] = (float)bce_merged;

            #pragma unroll
            for (int j = 0; j < 6; j++) g_acc[j] = 0.0;
            g_cnt = 0u;
        }
    }
}

extern "C" void kernel_launch(void* const* d_in, const int* in_sizes, int n_in,
                              void* d_out, int out_size) {
    const float* recon = (const float*)d_in[0];
    const float* x     = (const float*)d_in[1];
    const float* z     = (const float*)d_in[2];
    const float* mu    = (const float*)d_in[3];
    const float* lv    = (const float*)d_in[4];
    const float* text  = (const float*)d_in[5];
    const float* rec   = (const float*)d_in[6];
    const float* pmu   = (const float*)d_in[7];
    const float* plv   = (const float*)d_in[8];
    // d_in[9] = train_items, unused by the loss

    pass1_kernel<<<P1_GRID, P1_TPB>>>((const float4*)recon, (const float4*)x,
                                      (const float4*)text, (const float4*)rec);
    pass2_kernel<<<B_, 256>>>(z, mu, lv, pmu, plv, (float*)d_out);
}